// round 14
// baseline (speedup 1.0000x reference)
#include <cuda_runtime.h>
#include <cuda_bf16.h>
#include <cstdint>
#include <cmath>

#define BATCH 2
#define SEQ   2048
#define CH    1024
#define NH    16
#define SST   16
#define HDIM  64
#define NTOK  (BATCH*SEQ)   // 4096

#define NCH   64            // time chunks for parallel scan
#define CLEN  (SEQ/NCH)     // 32 steps per chunk
#define SGRP  16            // staging group (steps)

// ---------------- device scratch (allocation-free) --------------------------
__device__ float g_xb[(size_t)NTOK*CH];
__device__ float g_dl[(size_t)NTOK*CH];
__device__ float g_Bm[(size_t)NTOK*SST];
__device__ float g_Cm[(size_t)NTOK*SST];
__device__ float g_y [(size_t)NTOK*CH];
// parallel-scan intermediates
__device__ float g_hloc[(size_t)BATCH*NCH*CH*SST];
__device__ float g_hin [(size_t)BATCH*NCH*CH*SST];
__device__ float g_dsum[(size_t)BATCH*NCH*CH];
// bf16 split activations + transposed split weights
__device__ __nv_bfloat16 g_ahi[(size_t)NTOK*CH];
__device__ __nv_bfloat16 g_alo[(size_t)NTOK*CH];
__device__ __nv_bfloat16 g_wt [(size_t)12*CH*CH];  // 6 weights x {hi,lo}, [N][K]
// bf16 split QKV in (B,H,T,HD) layout
__device__ __nv_bfloat16 g_Qh[(size_t)NTOK*CH];
__device__ __nv_bfloat16 g_Ql[(size_t)NTOK*CH];
__device__ __nv_bfloat16 g_Kh[(size_t)NTOK*CH];
__device__ __nv_bfloat16 g_Kl[(size_t)NTOK*CH];
__device__ __nv_bfloat16 g_Vh[(size_t)NTOK*CH];
__device__ __nv_bfloat16 g_Vl[(size_t)NTOK*CH];

__device__ __forceinline__ float softplus_f(float x) {
    return (x > 20.f) ? x : log1pf(expf(x));
}

__device__ __forceinline__ uint32_t s2u(const void* p) {
    uint32_t a;
    asm("{ .reg .u64 t; cvta.to.shared.u64 t, %1; cvt.u32.u64 %0, t; }"
        : "=r"(a) : "l"(p));
    return a;
}

#define CP_ASYNC16(saddr, gptr) \
    asm volatile("cp.async.cg.shared.global [%0], [%1], 16;" \
                 :: "r"(saddr), "l"(gptr))
#define CP_COMMIT()  asm volatile("cp.async.commit_group;")
#define CP_WAIT1()   asm volatile("cp.async.wait_group 1;")
#define CP_WAIT0()   asm volatile("cp.async.wait_group 0;")

#define LDSM4(R0, R1, R2, R3, addr) \
    asm volatile("ldmatrix.sync.aligned.m8n8.x4.shared.b16 {%0,%1,%2,%3}, [%4];" \
                 : "=r"(R0), "=r"(R1), "=r"(R2), "=r"(R3) : "r"(addr))
#define LDSM4T(R0, R1, R2, R3, addr) \
    asm volatile("ldmatrix.sync.aligned.m8n8.x4.trans.shared.b16 {%0,%1,%2,%3}, [%4];" \
                 : "=r"(R0), "=r"(R1), "=r"(R2), "=r"(R3) : "r"(addr))

#define MMA16816(C, A0, A1, A2, A3, B0, B1) \
    asm volatile("mma.sync.aligned.m16n8k16.row.col.f32.bf16.bf16.f32 " \
                 "{%0,%1,%2,%3}, {%4,%5,%6,%7}, {%8,%9}, {%0,%1,%2,%3};" \
                 : "+f"((C)[0]), "+f"((C)[1]), "+f"((C)[2]), "+f"((C)[3]) \
                 : "r"(A0), "r"(A1), "r"(A2), "r"(A3), "r"(B0), "r"(B1))

// ============================================================================
// bf16-split tensor-core GEMM: out[4096,1024] = A @ W^T (+bias)
// 256 threads (8 warps, 2x4), CTA tile 128x128, warp tile 64x32.
// ============================================================================
#define MROWB  64
#define MTILE  (128*MROWB)
#define MSTG   (4*MTILE)
#define MM_SMEM (3*MSTG)

struct MMJob {
    const __nv_bfloat16* Bh;
    const __nv_bfloat16* Bl;
    const float* bias;
    float* out;
    __nv_bfloat16* oH;
    __nv_bfloat16* oL;
    int flags;
};

__device__ __forceinline__ uint32_t mm_swz(uint32_t r, uint32_t c16) {
    return r * MROWB + ((c16 ^ ((r >> 1) & 3)) << 4);
}

__global__ __launch_bounds__(256, 2)
void mm_multi(const __nv_bfloat16* __restrict__ Ahi,
              const __nv_bfloat16* __restrict__ Alo,
              MMJob j0, MMJob j1, MMJob j2)
{
    extern __shared__ char smem[];
    const MMJob j = (blockIdx.z == 0) ? j0 : ((blockIdx.z == 1) ? j1 : j2);

    const int tid  = threadIdx.x;
    const int wid  = tid >> 5, lane = tid & 31;
    const int m0 = blockIdx.y << 7, n0 = blockIdx.x << 7;
    const int wm = wid & 1, wn = wid >> 1;
    const uint32_t sbase = s2u(smem);

    const __nv_bfloat16* tp[4] = {Ahi, Alo, j.Bh, j.Bl};

    const int cr0 = tid >> 2, cs = tid & 3;
    const int cr1 = cr0 + 64;

    float acc[4][4][4];
    #pragma unroll
    for (int i = 0; i < 4; i++)
        #pragma unroll
        for (int jj = 0; jj < 4; jj++)
            #pragma unroll
            for (int q = 0; q < 4; q++) acc[i][jj][q] = 0.f;

    const uint32_t arow = (uint32_t)(wm * 64 + (lane & 15));
    const uint32_t acs  = (uint32_t)((lane >> 4) & 1);
    const uint32_t brow = (uint32_t)(wn * 32 + ((lane >> 4) & 1) * 8 + (lane & 7));
    const uint32_t bcs  = (uint32_t)((lane >> 3) & 1);

    #pragma unroll
    for (int st = 0; st < 3; st++) {
        const int k0 = st << 5;
        const uint32_t sb = sbase + st * MSTG;
        #pragma unroll
        for (int t = 0; t < 4; t++) {
            const int rb = (t < 2) ? m0 : n0;
            const __nv_bfloat16* g = tp[t];
            CP_ASYNC16(sb + t * MTILE + mm_swz(cr0, cs),
                       g + (size_t)(rb + cr0) * CH + k0 + cs * 8);
            CP_ASYNC16(sb + t * MTILE + mm_swz(cr1, cs),
                       g + (size_t)(rb + cr1) * CH + k0 + cs * 8);
        }
        CP_COMMIT();
    }

    const int NC = CH / 32;
    for (int ck = 0; ck < NC; ck++) {
        if (ck == NC - 1) CP_WAIT0(); else CP_WAIT1();
        __syncthreads();

        const uint32_t sb = sbase + (ck % 3) * MSTG;

        // ================= ks = 0 ===========================================
        {
            uint32_t a[4][4], bh[2][4], bl[2][4];
            #pragma unroll
            for (int i = 0; i < 4; i++)
                LDSM4(a[i][0], a[i][1], a[i][2], a[i][3],
                      sb + mm_swz(arow + i * 16, acs));
            #pragma unroll
            for (int jp = 0; jp < 2; jp++)
                LDSM4(bh[jp][0], bh[jp][1], bh[jp][2], bh[jp][3],
                      sb + 2 * MTILE + mm_swz(brow + jp * 16, bcs));
            #pragma unroll
            for (int i = 0; i < 4; i++)
                #pragma unroll
                for (int jj = 0; jj < 4; jj++)
                    MMA16816(acc[i][jj], a[i][0], a[i][1], a[i][2], a[i][3],
                             bh[jj >> 1][(jj & 1) * 2], bh[jj >> 1][(jj & 1) * 2 + 1]);
            #pragma unroll
            for (int jp = 0; jp < 2; jp++)
                LDSM4(bl[jp][0], bl[jp][1], bl[jp][2], bl[jp][3],
                      sb + 3 * MTILE + mm_swz(brow + jp * 16, bcs));
            #pragma unroll
            for (int i = 0; i < 4; i++)
                #pragma unroll
                for (int jj = 0; jj < 4; jj++)
                    MMA16816(acc[i][jj], a[i][0], a[i][1], a[i][2], a[i][3],
                             bl[jj >> 1][(jj & 1) * 2], bl[jj >> 1][(jj & 1) * 2 + 1]);
            #pragma unroll
            for (int i = 0; i < 4; i++)
                LDSM4(a[i][0], a[i][1], a[i][2], a[i][3],
                      sb + MTILE + mm_swz(arow + i * 16, acs));
            #pragma unroll
            for (int i = 0; i < 4; i++)
                #pragma unroll
                for (int jj = 0; jj < 4; jj++)
                    MMA16816(acc[i][jj], a[i][0], a[i][1], a[i][2], a[i][3],
                             bh[jj >> 1][(jj & 1) * 2], bh[jj >> 1][(jj & 1) * 2 + 1]);
        }

        if (ck >= 1 && ck + 2 < NC) {
            const int kc = ck + 2;
            const int k0 = kc << 5;
            const uint32_t sd = sbase + (kc % 3) * MSTG;
            #pragma unroll
            for (int t = 0; t < 4; t++) {
                const int rb = (t < 2) ? m0 : n0;
                const __nv_bfloat16* g = tp[t];
                CP_ASYNC16(sd + t * MTILE + mm_swz(cr0, cs),
                           g + (size_t)(rb + cr0) * CH + k0 + cs * 8);
                CP_ASYNC16(sd + t * MTILE + mm_swz(cr1, cs),
                           g + (size_t)(rb + cr1) * CH + k0 + cs * 8);
            }
        }
        CP_COMMIT();

        // ================= ks = 1 ===========================================
        {
            uint32_t a[4][4], bh[2][4], bl[2][4];
            #pragma unroll
            for (int i = 0; i < 4; i++)
                LDSM4(a[i][0], a[i][1], a[i][2], a[i][3],
                      sb + mm_swz(arow + i * 16, acs + 2));
            #pragma unroll
            for (int jp = 0; jp < 2; jp++)
                LDSM4(bh[jp][0], bh[jp][1], bh[jp][2], bh[jp][3],
                      sb + 2 * MTILE + mm_swz(brow + jp * 16, bcs + 2));
            #pragma unroll
            for (int i = 0; i < 4; i++)
                #pragma unroll
                for (int jj = 0; jj < 4; jj++)
                    MMA16816(acc[i][jj], a[i][0], a[i][1], a[i][2], a[i][3],
                             bh[jj >> 1][(jj & 1) * 2], bh[jj >> 1][(jj & 1) * 2 + 1]);
            #pragma unroll
            for (int jp = 0; jp < 2; jp++)
                LDSM4(bl[jp][0], bl[jp][1], bl[jp][2], bl[jp][3],
                      sb + 3 * MTILE + mm_swz(brow + jp * 16, bcs + 2));
            #pragma unroll
            for (int i = 0; i < 4; i++)
                #pragma unroll
                for (int jj = 0; jj < 4; jj++)
                    MMA16816(acc[i][jj], a[i][0], a[i][1], a[i][2], a[i][3],
                             bl[jj >> 1][(jj & 1) * 2], bl[jj >> 1][(jj & 1) * 2 + 1]);
            #pragma unroll
            for (int i = 0; i < 4; i++)
                LDSM4(a[i][0], a[i][1], a[i][2], a[i][3],
                      sb + MTILE + mm_swz(arow + i * 16, acs + 2));
            #pragma unroll
            for (int i = 0; i < 4; i++)
                #pragma unroll
                for (int jj = 0; jj < 4; jj++)
                    MMA16816(acc[i][jj], a[i][0], a[i][1], a[i][2], a[i][3],
                             bh[jj >> 1][(jj & 1) * 2], bh[jj >> 1][(jj & 1) * 2 + 1]);
        }
    }

    // ---- epilogue
    #pragma unroll
    for (int i = 0; i < 4; i++) {
        #pragma unroll
        for (int jj = 0; jj < 4; jj++) {
            const int row = m0 + wm * 64 + i * 16 + (lane >> 2);
            const int col = n0 + wn * 32 + jj * 8 + (lane & 3) * 2;
            float b0 = j.bias[col], b1 = j.bias[col + 1];
            float v0 = acc[i][jj][0] + b0, v1 = acc[i][jj][1] + b1;
            float v2 = acc[i][jj][2] + b0, v3 = acc[i][jj][3] + b1;
            if (j.flags & 1) {
                v0 = softplus_f(v0); v1 = softplus_f(v1);
                v2 = softplus_f(v2); v3 = softplus_f(v3);
            }
            if (j.flags & 4) {
                const int hh = col >> 6, hd = col & (HDIM - 1);
                const int bb0 = row >> 11, t0 = row & (SEQ - 1);
                size_t base0 = ((((size_t)bb0 * NH + hh) * SEQ) + t0) * HDIM + hd;
                const int r8 = row + 8;
                const int bb1 = r8 >> 11, t1 = r8 & (SEQ - 1);
                size_t base1 = ((((size_t)bb1 * NH + hh) * SEQ) + t1) * HDIM + hd;
                __nv_bfloat16 h0 = __float2bfloat16(v0);
                __nv_bfloat16 h1 = __float2bfloat16(v1);
                __nv_bfloat16 h2 = __float2bfloat16(v2);
                __nv_bfloat16 h3 = __float2bfloat16(v3);
                *(__nv_bfloat162*)(j.oH + base0) = __nv_bfloat162(h0, h1);
                *(__nv_bfloat162*)(j.oH + base1) = __nv_bfloat162(h2, h3);
                *(__nv_bfloat162*)(j.oL + base0) = __nv_bfloat162(
                    __float2bfloat16(v0 - __bfloat162float(h0)),
                    __float2bfloat16(v1 - __bfloat162float(h1)));
                *(__nv_bfloat162*)(j.oL + base1) = __nv_bfloat162(
                    __float2bfloat16(v2 - __bfloat162float(h2)),
                    __float2bfloat16(v3 - __bfloat162float(h3)));
            } else {
                *(float2*)(j.out + (size_t)row * CH + col)       = make_float2(v0, v1);
                *(float2*)(j.out + (size_t)(row + 8) * CH + col) = make_float2(v2, v3);
            }
        }
    }
}

// ---------------- fp32 -> bf16 hi/lo split (activations) --------------------
__global__ __launch_bounds__(256)
void cvt_act(const float* __restrict__ in, __nv_bfloat16* __restrict__ hi,
             __nv_bfloat16* __restrict__ lo)
{
    size_t i = ((size_t)blockIdx.x * 256 + threadIdx.x) * 4;
    float4 v = *(const float4*)(in + i);
    __nv_bfloat16 h0 = __float2bfloat16(v.x);
    __nv_bfloat16 h1 = __float2bfloat16(v.y);
    __nv_bfloat16 h2 = __float2bfloat16(v.z);
    __nv_bfloat16 h3 = __float2bfloat16(v.w);
    __nv_bfloat16 l0 = __float2bfloat16(v.x - __bfloat162float(h0));
    __nv_bfloat16 l1 = __float2bfloat16(v.y - __bfloat162float(h1));
    __nv_bfloat16 l2 = __float2bfloat16(v.z - __bfloat162float(h2));
    __nv_bfloat16 l3 = __float2bfloat16(v.w - __bfloat162float(h3));
    __nv_bfloat162* h2p = (__nv_bfloat162*)(hi + i);
    __nv_bfloat162* l2p = (__nv_bfloat162*)(lo + i);
    h2p[0] = __nv_bfloat162(h0, h1); h2p[1] = __nv_bfloat162(h2, h3);
    l2p[0] = __nv_bfloat162(l0, l1); l2p[1] = __nv_bfloat162(l2, l3);
}

// -------- 6-way weight transpose + hi/lo split: W[K][N] -> T[N][K] ----------
__global__ __launch_bounds__(256)
void cvt_wt6(const float* __restrict__ W0, const float* __restrict__ W1,
             const float* __restrict__ W2, const float* __restrict__ W3,
             const float* __restrict__ W4, const float* __restrict__ W5,
             __nv_bfloat16* __restrict__ wt)
{
    const float* Wp[6] = {W0, W1, W2, W3, W4, W5};
    const float* W = Wp[blockIdx.z];
    const size_t WSZ = (size_t)CH * CH;
    __nv_bfloat16* Th = wt + (size_t)blockIdx.z * 2 * WSZ;
    __nv_bfloat16* Tl = Th + WSZ;

    __shared__ float t[32][33];
    int tx = threadIdx.x, ty = threadIdx.y;
    int nb = blockIdx.x * 32, kb = blockIdx.y * 32;
    #pragma unroll
    for (int jj = 0; jj < 32; jj += 8)
        t[ty + jj][tx] = W[(size_t)(kb + ty + jj) * CH + nb + tx];
    __syncthreads();
    #pragma unroll
    for (int jj = 0; jj < 32; jj += 8) {
        float v = t[tx][ty + jj];
        __nv_bfloat16 h = __float2bfloat16(v);
        __nv_bfloat16 l = __float2bfloat16(v - __bfloat162float(h));
        size_t o = (size_t)(nb + ty + jj) * CH + kb + tx;
        Th[o] = h; Tl[o] = l;
    }
}

// ---------------- small B/C projection ---------------------------------------
__global__ __launch_bounds__(256)
void bc_k(const float* __restrict__ x, const float* __restrict__ WB,
          const float* __restrict__ WC, float* __restrict__ Bm,
          float* __restrict__ Cm)
{
    __shared__ float xs[8][64];
    __shared__ float Ws[64][32];
    const int tid = threadIdx.x;
    const int tx = tid & 31, ty = tid >> 5;
    const int tok0 = blockIdx.x * 8;
    float acc = 0.f;

    for (int k0 = 0; k0 < CH; k0 += 64) {
        __syncthreads();
        if (tid < 128) {
            int t = tid >> 4, c4 = (tid & 15) * 4;
            *(float4*)&xs[t][c4] =
                *(const float4*)&x[(size_t)(tok0 + t) * CH + k0 + c4];
        }
        {
            int r = tid >> 2, c = (tid & 3) * 4;
            *(float4*)&Ws[r][c]      = *(const float4*)&WB[(size_t)(k0 + r) * SST + c];
            *(float4*)&Ws[r][16 + c] = *(const float4*)&WC[(size_t)(k0 + r) * SST + c];
        }
        __syncthreads();
        #pragma unroll
        for (int k = 0; k < 64; k++)
            acc = fmaf(xs[ty][k], Ws[k][tx], acc);
    }
    int tok = tok0 + ty;
    if (tx < 16) Bm[(size_t)tok * SST + tx] = acc;
    else         Cm[(size_t)tok * SST + (tx - 16)] = acc;
}

// ---------------- parallel scan, phase 1 -------------------------------------
__global__ __launch_bounds__(64)
void scan1_k(const float* __restrict__ xb, const float* __restrict__ dl,
             const float* __restrict__ Bm, const float* __restrict__ A_log,
             float* __restrict__ hloc, float* __restrict__ dsum)
{
    __shared__ float sB[SGRP * SST];
    const int tid = threadIdx.x;
    const int b = blockIdx.z, ck = blockIdx.y;
    const int c = blockIdx.x * 64 + tid;
    const int t0 = ck * CLEN;

    float A[SST];
    #pragma unroll
    for (int s = 0; s < SST; s++) A[s] = -expf(A_log[(size_t)c * SST + s]);
    float h[SST];
    #pragma unroll
    for (int s = 0; s < SST; s++) h[s] = 0.f;
    float Ds = 0.f;

    for (int g = 0; g < CLEN; g += SGRP) {
        const int tg = t0 + g;
        float rd[SGRP], rx[SGRP];
        size_t base = ((size_t)(b * SEQ + tg)) * CH + c;
        #pragma unroll
        for (int i = 0; i < SGRP; i++) {
            rd[i] = dl[base + (size_t)i * CH];
            rx[i] = xb[base + (size_t)i * CH];
        }
        __syncthreads();
        {
            size_t bb = ((size_t)(b * SEQ + tg)) * SST;
            ((float4*)sB)[tid] = ((const float4*)(Bm + bb))[tid];
        }
        __syncthreads();
        #pragma unroll
        for (int i = 0; i < SGRP; i++) {
            float d = rd[i];
            float dx = d * rx[i];
            Ds += d;
            #pragma unroll
            for (int s = 0; s < SST; s++) {
                float bar = __expf(d * A[s]);
                h[s] = fmaf(bar, h[s], dx * sB[i * SST + s]);
            }
        }
    }
    size_t o = (((size_t)(b * NCH + ck)) * CH + c) * SST;
    #pragma unroll
    for (int s4 = 0; s4 < SST; s4 += 4)
        *(float4*)&hloc[o + s4] = make_float4(h[s4], h[s4+1], h[s4+2], h[s4+3]);
    dsum[((size_t)(b * NCH + ck)) * CH + c] = Ds;
}

// ---------------- parallel scan, phase 2 -------------------------------------
__global__ __launch_bounds__(128)
void scan2_k(const float* __restrict__ hloc, const float* __restrict__ dsum,
             const float* __restrict__ A_log, float* __restrict__ hin)
{
    const int lane = blockIdx.x * 128 + threadIdx.x;
    const int b = lane >> 10, c = lane & (CH - 1);

    float A[SST];
    #pragma unroll
    for (int s = 0; s < SST; s++) A[s] = -expf(A_log[(size_t)c * SST + s]);
    float h[SST];
    #pragma unroll
    for (int s = 0; s < SST; s++) h[s] = 0.f;

    for (int ck = 0; ck < NCH; ck++) {
        size_t o = (((size_t)(b * NCH + ck)) * CH + c) * SST;
        #pragma unroll
        for (int s4 = 0; s4 < SST; s4 += 4)
            *(float4*)&hin[o + s4] = make_float4(h[s4], h[s4+1], h[s4+2], h[s4+3]);
        float Ds = dsum[((size_t)(b * NCH + ck)) * CH + c];
        #pragma unroll
        for (int s4 = 0; s4 < SST; s4 += 4) {
            float4 hl = *(const float4*)&hloc[o + s4];
            h[s4+0] = fmaf(__expf(Ds * A[s4+0]), h[s4+0], hl.x);
            h[s4+1] = fmaf(__expf(Ds * A[s4+1]), h[s4+1], hl.y);
            h[s4+2] = fmaf(__expf(Ds * A[s4+2]), h[s4+2], hl.z);
            h[s4+3] = fmaf(__expf(Ds * A[s4+3]), h[s4+3], hl.w);
        }
    }
}

// ---------------- parallel scan, phase 3 -------------------------------------
__global__ __launch_bounds__(64)
void scan3_k(const float* __restrict__ xb, const float* __restrict__ dl,
             const float* __restrict__ Bm, const float* __restrict__ Cm,
             const float* __restrict__ A_log, const float* __restrict__ hin,
             float* __restrict__ y)
{
    __shared__ float sB[SGRP * SST];
    __shared__ float sC[SGRP * SST];
    const int tid = threadIdx.x;
    const int b = blockIdx.z, ck = blockIdx.y;
    const int c = blockIdx.x * 64 + tid;
    const int t0 = ck * CLEN;

    float A[SST];
    #pragma unroll
    for (int s = 0; s < SST; s++) A[s] = -expf(A_log[(size_t)c * SST + s]);
    float h[SST];
    {
        size_t o = (((size_t)(b * NCH + ck)) * CH + c) * SST;
        #pragma unroll
        for (int s4 = 0; s4 < SST; s4 += 4) {
            float4 v = *(const float4*)&hin[o + s4];
            h[s4] = v.x; h[s4+1] = v.y; h[s4+2] = v.z; h[s4+3] = v.w;
        }
    }

    for (int g = 0; g < CLEN; g += SGRP) {
        const int tg = t0 + g;
        float rd[SGRP], rx[SGRP];
        size_t base = ((size_t)(b * SEQ + tg)) * CH + c;
        #pragma unroll
        for (int i = 0; i < SGRP; i++) {
            rd[i] = dl[base + (size_t)i * CH];
            rx[i] = xb[base + (size_t)i * CH];
        }
        __syncthreads();
        {
            size_t bb = ((size_t)(b * SEQ + tg)) * SST;
            ((float4*)sB)[tid] = ((const float4*)(Bm + bb))[tid];
            ((float4*)sC)[tid] = ((const float4*)(Cm + bb))[tid];
        }
        __syncthreads();
        #pragma unroll
        for (int i = 0; i < SGRP; i++) {
            float d = rd[i];
            float dx = d * rx[i];
            float yv = 0.f;
            #pragma unroll
            for (int s = 0; s < SST; s++) {
                float bar = __expf(d * A[s]);
                float hh = fmaf(bar, h[s], dx * sB[i * SST + s]);
                h[s] = hh;
                yv = fmaf(hh, sC[i * SST + s], yv);
            }
            y[base + (size_t)i * CH] = yv;
        }
    }
}

// ----------- LayerNorm(x_base + y) -> bf16 hi/lo split directly -------------
__global__ __launch_bounds__(256)
void ln_k(const float* __restrict__ xb, const float* __restrict__ y,
          const float* __restrict__ gam, const float* __restrict__ bet,
          __nv_bfloat16* __restrict__ hi, __nv_bfloat16* __restrict__ lo)
{
    const int tok = blockIdx.x, tid = threadIdx.x;
    const float4* a4 = (const float4*)(xb + (size_t)tok * CH);
    const float4* b4 = (const float4*)(y  + (size_t)tok * CH);
    float4 v = a4[tid], w = b4[tid];
    v.x += w.x; v.y += w.y; v.z += w.z; v.w += w.w;
    float sum = v.x + v.y + v.z + v.w;
    float sq  = v.x * v.x + v.y * v.y + v.z * v.z + v.w * v.w;
    #pragma unroll
    for (int off = 16; off; off >>= 1) {
        sum += __shfl_xor_sync(0xffffffffu, sum, off);
        sq  += __shfl_xor_sync(0xffffffffu, sq,  off);
    }
    __shared__ float s1[8], s2[8];
    __shared__ float mu_s, rstd_s;
    if ((tid & 31) == 0) { s1[tid >> 5] = sum; s2[tid >> 5] = sq; }
    __syncthreads();
    if (tid == 0) {
        float t1 = 0.f, t2 = 0.f;
        #pragma unroll
        for (int i = 0; i < 8; i++) { t1 += s1[i]; t2 += s2[i]; }
        float mu = t1 * (1.f / CH);
        float var = t2 * (1.f / CH) - mu * mu;
        mu_s = mu;
        rstd_s = rsqrtf(var + 1e-5f);
    }
    __syncthreads();
    float mu = mu_s, rstd = rstd_s;
    float4 g = ((const float4*)gam)[tid];
    float4 be = ((const float4*)bet)[tid];
    float o0 = (v.x - mu) * rstd * g.x + be.x;
    float o1 = (v.y - mu) * rstd * g.y + be.y;
    float o2 = (v.z - mu) * rstd * g.z + be.z;
    float o3 = (v.w - mu) * rstd * g.w + be.w;
    __nv_bfloat16 h0 = __float2bfloat16(o0);
    __nv_bfloat16 h1 = __float2bfloat16(o1);
    __nv_bfloat16 h2 = __float2bfloat16(o2);
    __nv_bfloat16 h3 = __float2bfloat16(o3);
    size_t base = (size_t)tok * CH + tid * 4;
    __nv_bfloat162* hp = (__nv_bfloat162*)(hi + base);
    __nv_bfloat162* lp = (__nv_bfloat162*)(lo + base);
    hp[0] = __nv_bfloat162(h0, h1); hp[1] = __nv_bfloat162(h2, h3);
    lp[0] = __nv_bfloat162(__float2bfloat16(o0 - __bfloat162float(h0)),
                           __float2bfloat16(o1 - __bfloat162float(h1)));
    lp[1] = __nv_bfloat162(__float2bfloat16(o2 - __bfloat162float(h2)),
                           __float2bfloat16(o3 - __bfloat162float(h3)));
}

// ============================================================================
// Tensor-core causal flash attention, q-tile 128, 256 threads (8 warps).
// Epilogue emits bf16 hi/lo split (B,T,C).
// ============================================================================
#define FRS    144
#define FQTILE (128*FRS)                // Q tile (hi or lo): 18432 B
#define FTILE  (64*FRS)                 // K/V tile: 9216 B
#define FSTG   (4*FTILE)                // Kh, Kl, Vh, Vl: 36864 B
#define F_SMEM (2*FQTILE + 2*FSTG)      // 110592 B

__global__ __launch_bounds__(256, 2)
void flash_mma(const __nv_bfloat16* __restrict__ Qh,
               const __nv_bfloat16* __restrict__ Ql,
               const __nv_bfloat16* __restrict__ Kh,
               const __nv_bfloat16* __restrict__ Kl,
               const __nv_bfloat16* __restrict__ Vh,
               const __nv_bfloat16* __restrict__ Vl,
               const float* __restrict__ temp,
               __nv_bfloat16* __restrict__ oHi, __nv_bfloat16* __restrict__ oLo)
{
    extern __shared__ char smem[];
    const int tid = threadIdx.x;
    const int wid = tid >> 5, lane = tid & 31;
    const int qt = (int)gridDim.x - 1 - (int)blockIdx.x;  // reversed schedule
    const int bh = blockIdx.y;
    const int b = bh >> 4, h = bh & 15;
    const int q0 = qt << 7;                               // 128-row q tile
    const uint32_t sb = s2u(smem);
    const uint32_t sQ = sb;
    const uint32_t sS0 = sb + 2 * FQTILE;

    const float sc = softplus_f(temp[h]) * 0.125f;

    const __nv_bfloat16* Qhg = Qh + (size_t)bh * SEQ * HDIM + (size_t)q0 * HDIM;
    const __nv_bfloat16* Qlg = Ql + (size_t)bh * SEQ * HDIM + (size_t)q0 * HDIM;
    const __nv_bfloat16* kvg[4] = {
        Kh + (size_t)bh * SEQ * HDIM, Kl + (size_t)bh * SEQ * HDIM,
        Vh + (size_t)bh * SEQ * HDIM, Vl + (size_t)bh * SEQ * HDIM };

    const int kend = 2 * qt + 1;   // kb range: 0..kend

    // ---- prologue: Q (2 x 128 rows = 2048 slots), stage 0, stage 1
    #pragma unroll
    for (int i = 0; i < 8; i++) {
        int slot = tid + i * 256;               // 2048 slots
        int buf = slot >> 10, idx = slot & 1023; // 128 rows x 8 ch
        int row = idx >> 3, ch = idx & 7;
        const __nv_bfloat16* src = (buf ? Qlg : Qhg) + row * HDIM + ch * 8;
        CP_ASYNC16(sQ + buf * FQTILE + row * FRS + ch * 16, src);
    }
    {
        #pragma unroll
        for (int i = 0; i < 8; i++) {
            int slot = tid + i * 256;           // 2048 slots: 4 tiles x 512
            int buf = slot >> 9, idx = slot & 511;
            int row = idx >> 3, ch = idx & 7;
            CP_ASYNC16(sS0 + buf * FTILE + row * FRS + ch * 16,
                       kvg[buf] + row * HDIM + ch * 8);
        }
        CP_COMMIT();
    }
    if (kend >= 1) {
        #pragma unroll
        for (int i = 0; i < 8; i++) {
            int slot = tid + i * 256;
            int buf = slot >> 9, idx = slot & 511;
            int row = idx >> 3, ch = idx & 7;
            CP_ASYNC16(sS0 + FSTG + buf * FTILE + row * FRS + ch * 16,
                       kvg[buf] + (64 + row) * HDIM + ch * 8);
        }
        CP_COMMIT();
    }

    const uint32_t aoff = (uint32_t)(wid * 16 + (lane & 15)) * FRS
                        + ((lane >> 4) & 1) * 16;
    const uint32_t kboff = (uint32_t)(((lane >> 4) & 1) * 8 + (lane & 7)) * FRS
                         + ((lane >> 3) & 1) * 16;
    const uint32_t vtoff = (uint32_t)((lane & 7) + ((lane >> 3) & 1) * 8) * FRS
                         + ((lane >> 4) & 1) * 16;

    uint32_t qh[4][4], ql[4][4];
    float O[8][4];
    #pragma unroll
    for (int jj = 0; jj < 8; jj++)
        #pragma unroll
        for (int q = 0; q < 4; q++) O[jj][q] = 0.f;
    float m0v = -1e30f, m1v = -1e30f, l0v = 0.f, l1v = 0.f;

    const int r_in_w = lane >> 2;
    const int row0g = q0 + wid * 16 + r_in_w;
    const int cql = (lane & 3) * 2;

    for (int kb = 0; kb <= kend; kb++) {
        if (kb < kend) CP_WAIT1(); else CP_WAIT0();
        __syncthreads();

        if (kb == 0) {
            #pragma unroll
            for (int ks = 0; ks < 4; ks++) {
                LDSM4(qh[ks][0], qh[ks][1], qh[ks][2], qh[ks][3],
                      sQ + aoff + ks * 32);
                LDSM4(ql[ks][0], ql[ks][1], ql[ks][2], ql[ks][3],
                      sQ + FQTILE + aoff + ks * 32);
            }
        }

        const uint32_t st = sS0 + (kb & 1) * FSTG;
        float S[8][4];
        #pragma unroll
        for (int jj = 0; jj < 8; jj++)
            #pragma unroll
            for (int q = 0; q < 4; q++) S[jj][q] = 0.f;

        #pragma unroll
        for (int ks = 0; ks < 4; ks++) {
            #pragma unroll
            for (int g = 0; g < 4; g++) {
                uint32_t bh0, bh1, bh2, bh3, bl0, bl1, bl2, bl3;
                uint32_t kaddr = st + kboff + g * 16 * FRS + ks * 32;
                LDSM4(bh0, bh1, bh2, bh3, kaddr);
                LDSM4(bl0, bl1, bl2, bl3, kaddr + FTILE);
                MMA16816(S[2*g],   qh[ks][0], qh[ks][1], qh[ks][2], qh[ks][3], bh0, bh1);
                MMA16816(S[2*g+1], qh[ks][0], qh[ks][1], qh[ks][2], qh[ks][3], bh2, bh3);
                MMA16816(S[2*g],   qh[ks][0], qh[ks][1], qh[ks][2], qh[ks][3], bl0, bl1);
                MMA16816(S[2*g+1], qh[ks][0], qh[ks][1], qh[ks][2], qh[ks][3], bl2, bl3);
                MMA16816(S[2*g],   ql[ks][0], ql[ks][1], ql[ks][2], ql[ks][3], bh0, bh1);
                MMA16816(S[2*g+1], ql[ks][0], ql[ks][1], ql[ks][2], ql[ks][3], bh2, bh3);
            }
        }

        #pragma unroll
        for (int jj = 0; jj < 8; jj++)
            #pragma unroll
            for (int q = 0; q < 4; q++) S[jj][q] *= sc;
        if (kb >= 2 * qt) {   // mask only on blocks overlapping the diagonal
            #pragma unroll
            for (int jj = 0; jj < 8; jj++) {
                #pragma unroll
                for (int q = 0; q < 4; q++) {
                    int col = (kb << 6) + jj * 8 + cql + (q & 1);
                    int row = row0g + (q >> 1) * 8;
                    if (col > row) S[jj][q] = -1e30f;
                }
            }
        }

        float mx0 = -1e30f, mx1 = -1e30f;
        #pragma unroll
        for (int jj = 0; jj < 8; jj++) {
            mx0 = fmaxf(mx0, fmaxf(S[jj][0], S[jj][1]));
            mx1 = fmaxf(mx1, fmaxf(S[jj][2], S[jj][3]));
        }
        mx0 = fmaxf(mx0, __shfl_xor_sync(0xffffffffu, mx0, 1));
        mx0 = fmaxf(mx0, __shfl_xor_sync(0xffffffffu, mx0, 2));
        mx1 = fmaxf(mx1, __shfl_xor_sync(0xffffffffu, mx1, 1));
        mx1 = fmaxf(mx1, __shfl_xor_sync(0xffffffffu, mx1, 2));
        float mn0 = fmaxf(m0v, mx0), mn1 = fmaxf(m1v, mx1);
        float fac0 = __expf(m0v - mn0), fac1 = __expf(m1v - mn1);
        m0v = mn0; m1v = mn1;
        float rs0 = 0.f, rs1 = 0.f;
        #pragma unroll
        for (int jj = 0; jj < 8; jj++) {
            S[jj][0] = __expf(S[jj][0] - mn0); rs0 += S[jj][0];
            S[jj][1] = __expf(S[jj][1] - mn0); rs0 += S[jj][1];
            S[jj][2] = __expf(S[jj][2] - mn1); rs1 += S[jj][2];
            S[jj][3] = __expf(S[jj][3] - mn1); rs1 += S[jj][3];
        }
        rs0 += __shfl_xor_sync(0xffffffffu, rs0, 1);
        rs0 += __shfl_xor_sync(0xffffffffu, rs0, 2);
        rs1 += __shfl_xor_sync(0xffffffffu, rs1, 1);
        rs1 += __shfl_xor_sync(0xffffffffu, rs1, 2);
        l0v = l0v * fac0 + rs0;
        l1v = l1v * fac1 + rs1;
        #pragma unroll
        for (int jj = 0; jj < 8; jj++) {
            O[jj][0] *= fac0; O[jj][1] *= fac0;
            O[jj][2] *= fac1; O[jj][3] *= fac1;
        }

        #pragma unroll
        for (int ks = 0; ks < 4; ks++) {
            uint32_t ph[4], pl[4];
            #pragma unroll
            for (int half = 0; half < 2; half++) {
                int jj = 2 * ks + half;
                float f0 = S[jj][0], f1 = S[jj][1], f2 = S[jj][2], f3 = S[jj][3];
                __nv_bfloat162 h01 = __floats2bfloat162_rn(f0, f1);
                __nv_bfloat162 h23 = __floats2bfloat162_rn(f2, f3);
                __nv_bfloat162 l01 = __floats2bfloat162_rn(
                    f0 - __bfloat162float(h01.x), f1 - __bfloat162float(h01.y));
                __nv_bfloat162 l23 = __floats2bfloat162_rn(
                    f2 - __bfloat162float(h23.x), f3 - __bfloat162float(h23.y));
                if (half == 0) {
                    ph[0] = *(uint32_t*)&h01; ph[1] = *(uint32_t*)&h23;
                    pl[0] = *(uint32_t*)&l01; pl[1] = *(uint32_t*)&l23;
                } else {
                    ph[2] = *(uint32_t*)&h01; ph[3] = *(uint32_t*)&h23;
                    pl[2] = *(uint32_t*)&l01; pl[3] = *(uint32_t*)&l23;
                }
            }
            #pragma unroll
            for (int g = 0; g < 4; g++) {
                uint32_t vh0, vh1, vh2, vh3, vl0, vl1, vl2, vl3;
                uint32_t vaddr = st + 2 * FTILE + vtoff + ks * 16 * FRS + g * 32;
                LDSM4T(vh0, vh1, vh2, vh3, vaddr);
                LDSM4T(vl0, vl1, vl2, vl3, vaddr + FTILE);
                MMA16816(O[2*g],   ph[0], ph[1], ph[2], ph[3], vh0, vh1);
                MMA16816(O[2*g+1], ph[0], ph[1], ph[2], ph[3], vh2, vh3);
                MMA16816(O[2*g],   ph[0], ph[1], ph[2], ph[3], vl0, vl1);
                MMA16816(O[2*g+1], ph[0], ph[1], ph[2], ph[3], vl2, vl3);
                MMA16816(O[2*g],   pl[0], pl[1], pl[2], pl[3], vh0, vh1);
                MMA16816(O[2*g+1], pl[0], pl[1], pl[2], pl[3], vh2, vh3);
            }
        }
        __syncthreads();

        if (kb + 2 <= kend) {
            const uint32_t sd = sS0 + (kb & 1) * FSTG;
            const int kr = (kb + 2) << 6;
            #pragma unroll
            for (int i = 0; i < 8; i++) {
                int slot = tid + i * 256;
                int buf = slot >> 9, idx = slot & 511;
                int row = idx >> 3, ch = idx & 7;
                CP_ASYNC16(sd + buf * FTILE + row * FRS + ch * 16,
                           kvg[buf] + (size_t)(kr + row) * HDIM + ch * 8);
            }
            CP_COMMIT();
        }
    }

    float inv0 = 1.f / l0v, inv1 = 1.f / l1v;
    const int row_a = row0g, row_b = row0g + 8;
    #pragma unroll
    for (int jj = 0; jj < 8; jj++) {
        int col = h * HDIM + jj * 8 + cql;
        float a0 = O[jj][0] * inv0, a1 = O[jj][1] * inv0;
        float b0 = O[jj][2] * inv1, b1 = O[jj][3] * inv1;
        __nv_bfloat162 ha = __floats2bfloat162_rn(a0, a1);
        __nv_bfloat162 hb = __floats2bfloat162_rn(b0, b1);
        size_t pa = ((size_t)(b * SEQ + row_a)) * CH + col;
        size_t pb = ((size_t)(b * SEQ + row_b)) * CH + col;
        *(__nv_bfloat162*)(oHi + pa) = ha;
        *(__nv_bfloat162*)(oHi + pb) = hb;
        *(__nv_bfloat162*)(oLo + pa) = __floats2bfloat162_rn(
            a0 - __bfloat162float(ha.x), a1 - __bfloat162float(ha.y));
        *(__nv_bfloat162*)(oLo + pb) = __floats2bfloat162_rn(
            b0 - __bfloat162float(hb.x), b1 - __bfloat162float(hb.y));
    }
}

// ---------------- launcher ---------------------------------------------------
extern "C" void kernel_launch(void* const* d_in, const int* in_sizes, int n_in,
                              void* d_out, int out_size)
{
    const float* x     = (const float*)d_in[0];
    const float* A_log = (const float*)d_in[1];
    const float* Wd    = (const float*)d_in[2];
    const float* bd    = (const float*)d_in[3];
    const float* WB    = (const float*)d_in[4];
    const float* WC    = (const float*)d_in[5];
    const float* Wq    = (const float*)d_in[6];
    const float* bq    = (const float*)d_in[7];
    const float* Wk    = (const float*)d_in[8];
    const float* bk    = (const float*)d_in[9];
    const float* Wv    = (const float*)d_in[10];
    const float* bv    = (const float*)d_in[11];
    const float* Wx    = (const float*)d_in[12];
    const float* bx    = (const float*)d_in[13];
    const float* Wo    = (const float*)d_in[14];
    const float* bo    = (const float*)d_in[15];
    const float* ln_g  = (const float*)d_in[16];
    const float* ln_b  = (const float*)d_in[17];
    const float* temp  = (const float*)d_in[18];
    float* out = (float*)d_out;

    float* xb = nullptr; cudaGetSymbolAddress((void**)&xb, g_xb);
    float* dl = nullptr; cudaGetSymbolAddress((void**)&dl, g_dl);
    float* Bm = nullptr; cudaGetSymbolAddress((void**)&Bm, g_Bm);
    float* Cm = nullptr; cudaGetSymbolAddress((void**)&Cm, g_Cm);
    float* yb = nullptr; cudaGetSymbolAddress((void**)&yb, g_y);
    float* hloc = nullptr; cudaGetSymbolAddress((void**)&hloc, g_hloc);
    float* hin  = nullptr; cudaGetSymbolAddress((void**)&hin,  g_hin);
    float* dsum = nullptr; cudaGetSymbolAddress((void**)&dsum, g_dsum);
    __nv_bfloat16* ahi = nullptr; cudaGetSymbolAddress((void**)&ahi, g_ahi);
    __nv_bfloat16* alo = nullptr; cudaGetSymbolAddress((void**)&alo, g_alo);
    __nv_bfloat16* wt  = nullptr; cudaGetSymbolAddress((void**)&wt,  g_wt);
    __nv_bfloat16 *qh, *ql, *kh, *kl, *vh, *vl;
    cudaGetSymbolAddress((void**)&qh, g_Qh);
    cudaGetSymbolAddress((void**)&ql, g_Ql);
    cudaGetSymbolAddress((void**)&kh, g_Kh);
    cudaGetSymbolAddress((void**)&kl, g_Kl);
    cudaGetSymbolAddress((void**)&vh, g_Vh);
    cudaGetSymbolAddress((void**)&vl, g_Vl);

    cudaFuncSetAttribute(mm_multi, cudaFuncAttributeMaxDynamicSharedMemorySize,
                         MM_SMEM);
    cudaFuncSetAttribute(flash_mma, cudaFuncAttributeMaxDynamicSharedMemorySize,
                         F_SMEM);

    const size_t WSZ = (size_t)CH * CH;

    // weight order in g_wt: {Wx, Wd, Wq, Wk, Wv, Wo} x {hi, lo}
    cvt_wt6<<<dim3(32, 32, 6), dim3(32, 8)>>>(Wx, Wd, Wq, Wk, Wv, Wo, wt);
    cvt_act<<<NTOK * CH / 1024, 256>>>(x, ahi, alo);
    bc_k<<<NTOK / 8, 256>>>(x, WB, WC, Bm, Cm);

    MMJob jx  = {wt + 0*WSZ,  wt + 1*WSZ,  bx, xb, nullptr, nullptr, 0};
    MMJob jd  = {wt + 2*WSZ,  wt + 3*WSZ,  bd, dl, nullptr, nullptr, 1};
    MMJob jq  = {wt + 4*WSZ,  wt + 5*WSZ,  bq, nullptr, qh, ql, 4};
    MMJob jk  = {wt + 6*WSZ,  wt + 7*WSZ,  bk, nullptr, kh, kl, 4};
    MMJob jv  = {wt + 8*WSZ,  wt + 9*WSZ,  bv, nullptr, vh, vl, 4};
    MMJob jo  = {wt + 10*WSZ, wt + 11*WSZ, bo, out, nullptr, nullptr, 0};
    MMJob jz  = {};

    mm_multi<<<dim3(8, 32, 2), 256, MM_SMEM>>>(ahi, alo, jx, jd, jz);

    dim3 scan_grid(CH / 64, NCH, BATCH);
    scan1_k<<<scan_grid, 64>>>(xb, dl, Bm, A_log, hloc, dsum);
    scan2_k<<<BATCH * CH / 128, 128>>>(hloc, dsum, A_log, hin);
    scan3_k<<<scan_grid, 64>>>(xb, dl, Bm, Cm, A_log, hin, yb);

    ln_k<<<NTOK, 256>>>(xb, yb, ln_g, ln_b, ahi, alo);

    mm_multi<<<dim3(8, 32, 3), 256, MM_SMEM>>>(ahi, alo, jq, jk, jv);

    flash_mma<<<dim3(SEQ / 128, BATCH * NH), 256, F_SMEM>>>(qh, ql, kh, kl,
                                                            vh, vl, temp,
                                                            ahi, alo);

    mm_multi<<<dim3(8, 32, 1), 256, MM_SMEM>>>(ahi, alo, jo, jz, jz);
}

// round 15
// speedup vs baseline: 1.0436x; 1.0436x over previous
#include <cuda_runtime.h>
#include <cuda_bf16.h>
#include <cstdint>
#include <cmath>

#define BATCH 2
#define SEQ   2048
#define CH    1024
#define NH    16
#define SST   16
#define HDIM  64
#define NTOK  (BATCH*SEQ)   // 4096

#define NCH   64            // time chunks for parallel scan
#define CLEN  (SEQ/NCH)     // 32 steps per chunk
#define SGRP  16            // staging group (steps)

// ---------------- device scratch (allocation-free) --------------------------
__device__ float g_xb[(size_t)NTOK*CH];
__device__ float g_dl[(size_t)NTOK*CH];
__device__ float g_Bm[(size_t)NTOK*SST];
__device__ float g_Cm[(size_t)NTOK*SST];
__device__ float g_y [(size_t)NTOK*CH];
// parallel-scan intermediates
__device__ float g_hloc[(size_t)BATCH*NCH*CH*SST];
__device__ float g_hin [(size_t)BATCH*NCH*CH*SST];
__device__ float g_dsum[(size_t)BATCH*NCH*CH];
// bf16 split activations + transposed split weights
__device__ __nv_bfloat16 g_ahi[(size_t)NTOK*CH];
__device__ __nv_bfloat16 g_alo[(size_t)NTOK*CH];
__device__ __nv_bfloat16 g_wt [(size_t)12*CH*CH];  // 6 weights x {hi,lo}, [N][K]
// bf16 split QKV in (B,H,T,HD) layout
__device__ __nv_bfloat16 g_Qh[(size_t)NTOK*CH];
__device__ __nv_bfloat16 g_Ql[(size_t)NTOK*CH];
__device__ __nv_bfloat16 g_Kh[(size_t)NTOK*CH];
__device__ __nv_bfloat16 g_Kl[(size_t)NTOK*CH];
__device__ __nv_bfloat16 g_Vh[(size_t)NTOK*CH];
__device__ __nv_bfloat16 g_Vl[(size_t)NTOK*CH];

__device__ __forceinline__ float softplus_f(float x) {
    return (x > 20.f) ? x : log1pf(expf(x));
}

__device__ __forceinline__ uint32_t s2u(const void* p) {
    uint32_t a;
    asm("{ .reg .u64 t; cvta.to.shared.u64 t, %1; cvt.u32.u64 %0, t; }"
        : "=r"(a) : "l"(p));
    return a;
}

#define CP_ASYNC16(saddr, gptr) \
    asm volatile("cp.async.cg.shared.global [%0], [%1], 16;" \
                 :: "r"(saddr), "l"(gptr))
#define CP_COMMIT()  asm volatile("cp.async.commit_group;")
#define CP_WAIT1()   asm volatile("cp.async.wait_group 1;")
#define CP_WAIT0()   asm volatile("cp.async.wait_group 0;")

#define LDSM4(R0, R1, R2, R3, addr) \
    asm volatile("ldmatrix.sync.aligned.m8n8.x4.shared.b16 {%0,%1,%2,%3}, [%4];" \
                 : "=r"(R0), "=r"(R1), "=r"(R2), "=r"(R3) : "r"(addr))
#define LDSM4T(R0, R1, R2, R3, addr) \
    asm volatile("ldmatrix.sync.aligned.m8n8.x4.trans.shared.b16 {%0,%1,%2,%3}, [%4];" \
                 : "=r"(R0), "=r"(R1), "=r"(R2), "=r"(R3) : "r"(addr))

#define MMA16816(C, A0, A1, A2, A3, B0, B1) \
    asm volatile("mma.sync.aligned.m16n8k16.row.col.f32.bf16.bf16.f32 " \
                 "{%0,%1,%2,%3}, {%4,%5,%6,%7}, {%8,%9}, {%0,%1,%2,%3};" \
                 : "+f"((C)[0]), "+f"((C)[1]), "+f"((C)[2]), "+f"((C)[3]) \
                 : "r"(A0), "r"(A1), "r"(A2), "r"(A3), "r"(B0), "r"(B1))

// ============================================================================
// bf16-split tensor-core GEMM: out[4096,1024] = A @ W^T (+bias)
// 256 threads (8 warps, 2x4), CTA tile 128x128, warp tile 64x32.
// ============================================================================
#define MROWB  64
#define MTILE  (128*MROWB)
#define MSTG   (4*MTILE)
#define MM_SMEM (3*MSTG)

struct MMJob {
    const __nv_bfloat16* Bh;
    const __nv_bfloat16* Bl;
    const float* bias;
    float* out;
    __nv_bfloat16* oH;
    __nv_bfloat16* oL;
    int flags;
};

__device__ __forceinline__ uint32_t mm_swz(uint32_t r, uint32_t c16) {
    return r * MROWB + ((c16 ^ ((r >> 1) & 3)) << 4);
}

__global__ __launch_bounds__(256, 2)
void mm_multi(const __nv_bfloat16* __restrict__ Ahi,
              const __nv_bfloat16* __restrict__ Alo,
              MMJob j0, MMJob j1, MMJob j2)
{
    extern __shared__ char smem[];
    const MMJob j = (blockIdx.z == 0) ? j0 : ((blockIdx.z == 1) ? j1 : j2);

    const int tid  = threadIdx.x;
    const int wid  = tid >> 5, lane = tid & 31;
    const int m0 = blockIdx.y << 7, n0 = blockIdx.x << 7;
    const int wm = wid & 1, wn = wid >> 1;
    const uint32_t sbase = s2u(smem);

    const __nv_bfloat16* tp[4] = {Ahi, Alo, j.Bh, j.Bl};

    const int cr0 = tid >> 2, cs = tid & 3;
    const int cr1 = cr0 + 64;

    float acc[4][4][4];
    #pragma unroll
    for (int i = 0; i < 4; i++)
        #pragma unroll
        for (int jj = 0; jj < 4; jj++)
            #pragma unroll
            for (int q = 0; q < 4; q++) acc[i][jj][q] = 0.f;

    const uint32_t arow = (uint32_t)(wm * 64 + (lane & 15));
    const uint32_t acs  = (uint32_t)((lane >> 4) & 1);
    const uint32_t brow = (uint32_t)(wn * 32 + ((lane >> 4) & 1) * 8 + (lane & 7));
    const uint32_t bcs  = (uint32_t)((lane >> 3) & 1);

    #pragma unroll
    for (int st = 0; st < 3; st++) {
        const int k0 = st << 5;
        const uint32_t sb = sbase + st * MSTG;
        #pragma unroll
        for (int t = 0; t < 4; t++) {
            const int rb = (t < 2) ? m0 : n0;
            const __nv_bfloat16* g = tp[t];
            CP_ASYNC16(sb + t * MTILE + mm_swz(cr0, cs),
                       g + (size_t)(rb + cr0) * CH + k0 + cs * 8);
            CP_ASYNC16(sb + t * MTILE + mm_swz(cr1, cs),
                       g + (size_t)(rb + cr1) * CH + k0 + cs * 8);
        }
        CP_COMMIT();
    }

    const int NC = CH / 32;
    for (int ck = 0; ck < NC; ck++) {
        if (ck == NC - 1) CP_WAIT0(); else CP_WAIT1();
        __syncthreads();

        const uint32_t sb = sbase + (ck % 3) * MSTG;

        // ================= ks = 0 ===========================================
        {
            uint32_t a[4][4], bh[2][4], bl[2][4];
            #pragma unroll
            for (int i = 0; i < 4; i++)
                LDSM4(a[i][0], a[i][1], a[i][2], a[i][3],
                      sb + mm_swz(arow + i * 16, acs));
            #pragma unroll
            for (int jp = 0; jp < 2; jp++)
                LDSM4(bh[jp][0], bh[jp][1], bh[jp][2], bh[jp][3],
                      sb + 2 * MTILE + mm_swz(brow + jp * 16, bcs));
            #pragma unroll
            for (int i = 0; i < 4; i++)
                #pragma unroll
                for (int jj = 0; jj < 4; jj++)
                    MMA16816(acc[i][jj], a[i][0], a[i][1], a[i][2], a[i][3],
                             bh[jj >> 1][(jj & 1) * 2], bh[jj >> 1][(jj & 1) * 2 + 1]);
            #pragma unroll
            for (int jp = 0; jp < 2; jp++)
                LDSM4(bl[jp][0], bl[jp][1], bl[jp][2], bl[jp][3],
                      sb + 3 * MTILE + mm_swz(brow + jp * 16, bcs));
            #pragma unroll
            for (int i = 0; i < 4; i++)
                #pragma unroll
                for (int jj = 0; jj < 4; jj++)
                    MMA16816(acc[i][jj], a[i][0], a[i][1], a[i][2], a[i][3],
                             bl[jj >> 1][(jj & 1) * 2], bl[jj >> 1][(jj & 1) * 2 + 1]);
            #pragma unroll
            for (int i = 0; i < 4; i++)
                LDSM4(a[i][0], a[i][1], a[i][2], a[i][3],
                      sb + MTILE + mm_swz(arow + i * 16, acs));
            #pragma unroll
            for (int i = 0; i < 4; i++)
                #pragma unroll
                for (int jj = 0; jj < 4; jj++)
                    MMA16816(acc[i][jj], a[i][0], a[i][1], a[i][2], a[i][3],
                             bh[jj >> 1][(jj & 1) * 2], bh[jj >> 1][(jj & 1) * 2 + 1]);
        }

        if (ck >= 1 && ck + 2 < NC) {
            const int kc = ck + 2;
            const int k0 = kc << 5;
            const uint32_t sd = sbase + (kc % 3) * MSTG;
            #pragma unroll
            for (int t = 0; t < 4; t++) {
                const int rb = (t < 2) ? m0 : n0;
                const __nv_bfloat16* g = tp[t];
                CP_ASYNC16(sd + t * MTILE + mm_swz(cr0, cs),
                           g + (size_t)(rb + cr0) * CH + k0 + cs * 8);
                CP_ASYNC16(sd + t * MTILE + mm_swz(cr1, cs),
                           g + (size_t)(rb + cr1) * CH + k0 + cs * 8);
            }
        }
        CP_COMMIT();

        // ================= ks = 1 ===========================================
        {
            uint32_t a[4][4], bh[2][4], bl[2][4];
            #pragma unroll
            for (int i = 0; i < 4; i++)
                LDSM4(a[i][0], a[i][1], a[i][2], a[i][3],
                      sb + mm_swz(arow + i * 16, acs + 2));
            #pragma unroll
            for (int jp = 0; jp < 2; jp++)
                LDSM4(bh[jp][0], bh[jp][1], bh[jp][2], bh[jp][3],
                      sb + 2 * MTILE + mm_swz(brow + jp * 16, bcs + 2));
            #pragma unroll
            for (int i = 0; i < 4; i++)
                #pragma unroll
                for (int jj = 0; jj < 4; jj++)
                    MMA16816(acc[i][jj], a[i][0], a[i][1], a[i][2], a[i][3],
                             bh[jj >> 1][(jj & 1) * 2], bh[jj >> 1][(jj & 1) * 2 + 1]);
            #pragma unroll
            for (int jp = 0; jp < 2; jp++)
                LDSM4(bl[jp][0], bl[jp][1], bl[jp][2], bl[jp][3],
                      sb + 3 * MTILE + mm_swz(brow + jp * 16, bcs + 2));
            #pragma unroll
            for (int i = 0; i < 4; i++)
                #pragma unroll
                for (int jj = 0; jj < 4; jj++)
                    MMA16816(acc[i][jj], a[i][0], a[i][1], a[i][2], a[i][3],
                             bl[jj >> 1][(jj & 1) * 2], bl[jj >> 1][(jj & 1) * 2 + 1]);
            #pragma unroll
            for (int i = 0; i < 4; i++)
                LDSM4(a[i][0], a[i][1], a[i][2], a[i][3],
                      sb + MTILE + mm_swz(arow + i * 16, acs + 2));
            #pragma unroll
            for (int i = 0; i < 4; i++)
                #pragma unroll
                for (int jj = 0; jj < 4; jj++)
                    MMA16816(acc[i][jj], a[i][0], a[i][1], a[i][2], a[i][3],
                             bh[jj >> 1][(jj & 1) * 2], bh[jj >> 1][(jj & 1) * 2 + 1]);
        }
    }

    // ---- epilogue
    #pragma unroll
    for (int i = 0; i < 4; i++) {
        #pragma unroll
        for (int jj = 0; jj < 4; jj++) {
            const int row = m0 + wm * 64 + i * 16 + (lane >> 2);
            const int col = n0 + wn * 32 + jj * 8 + (lane & 3) * 2;
            float b0 = j.bias[col], b1 = j.bias[col + 1];
            float v0 = acc[i][jj][0] + b0, v1 = acc[i][jj][1] + b1;
            float v2 = acc[i][jj][2] + b0, v3 = acc[i][jj][3] + b1;
            if (j.flags & 1) {
                v0 = softplus_f(v0); v1 = softplus_f(v1);
                v2 = softplus_f(v2); v3 = softplus_f(v3);
            }
            if (j.flags & 4) {
                const int hh = col >> 6, hd = col & (HDIM - 1);
                const int bb0 = row >> 11, t0 = row & (SEQ - 1);
                size_t base0 = ((((size_t)bb0 * NH + hh) * SEQ) + t0) * HDIM + hd;
                const int r8 = row + 8;
                const int bb1 = r8 >> 11, t1 = r8 & (SEQ - 1);
                size_t base1 = ((((size_t)bb1 * NH + hh) * SEQ) + t1) * HDIM + hd;
                __nv_bfloat16 h0 = __float2bfloat16(v0);
                __nv_bfloat16 h1 = __float2bfloat16(v1);
                __nv_bfloat16 h2 = __float2bfloat16(v2);
                __nv_bfloat16 h3 = __float2bfloat16(v3);
                *(__nv_bfloat162*)(j.oH + base0) = __nv_bfloat162(h0, h1);
                *(__nv_bfloat162*)(j.oH + base1) = __nv_bfloat162(h2, h3);
                *(__nv_bfloat162*)(j.oL + base0) = __nv_bfloat162(
                    __float2bfloat16(v0 - __bfloat162float(h0)),
                    __float2bfloat16(v1 - __bfloat162float(h1)));
                *(__nv_bfloat162*)(j.oL + base1) = __nv_bfloat162(
                    __float2bfloat16(v2 - __bfloat162float(h2)),
                    __float2bfloat16(v3 - __bfloat162float(h3)));
            } else {
                *(float2*)(j.out + (size_t)row * CH + col)       = make_float2(v0, v1);
                *(float2*)(j.out + (size_t)(row + 8) * CH + col) = make_float2(v2, v3);
            }
        }
    }
}

// -------- 6-way weight transpose + hi/lo split: W[K][N] -> T[N][K] ----------
__global__ __launch_bounds__(256)
void cvt_wt6(const float* __restrict__ W0, const float* __restrict__ W1,
             const float* __restrict__ W2, const float* __restrict__ W3,
             const float* __restrict__ W4, const float* __restrict__ W5,
             __nv_bfloat16* __restrict__ wt)
{
    const float* Wp[6] = {W0, W1, W2, W3, W4, W5};
    const float* W = Wp[blockIdx.z];
    const size_t WSZ = (size_t)CH * CH;
    __nv_bfloat16* Th = wt + (size_t)blockIdx.z * 2 * WSZ;
    __nv_bfloat16* Tl = Th + WSZ;

    __shared__ float t[32][33];
    int tx = threadIdx.x, ty = threadIdx.y;
    int nb = blockIdx.x * 32, kb = blockIdx.y * 32;
    #pragma unroll
    for (int jj = 0; jj < 32; jj += 8)
        t[ty + jj][tx] = W[(size_t)(kb + ty + jj) * CH + nb + tx];
    __syncthreads();
    #pragma unroll
    for (int jj = 0; jj < 32; jj += 8) {
        float v = t[tx][ty + jj];
        __nv_bfloat16 h = __float2bfloat16(v);
        __nv_bfloat16 l = __float2bfloat16(v - __bfloat162float(h));
        size_t o = (size_t)(nb + ty + jj) * CH + kb + tx;
        Th[o] = h; Tl[o] = l;
    }
}

// -------- fused: B/C projection + x -> bf16 hi/lo split ----------------------
// grid NTOK/8, 256 threads.  Per block: 8 tokens.
__global__ __launch_bounds__(256)
void prep_k(const float* __restrict__ x, const float* __restrict__ WB,
            const float* __restrict__ WC, float* __restrict__ Bm,
            float* __restrict__ Cm,
            __nv_bfloat16* __restrict__ hi, __nv_bfloat16* __restrict__ lo)
{
    __shared__ float xs[8][64];
    __shared__ float Ws[64][32];
    const int tid = threadIdx.x;
    const int tx = tid & 31, ty = tid >> 5;
    const int tok0 = blockIdx.x * 8;
    // split-emission mapping: thread -> (token, column pair)
    const int et = tid >> 5;            // token 0..7
    const int ec = (tid & 31) * 2;      // col pair base within 64-tile
    float acc = 0.f;

    for (int k0 = 0; k0 < CH; k0 += 64) {
        __syncthreads();
        if (tid < 128) {
            int t = tid >> 4, c4 = (tid & 15) * 4;
            *(float4*)&xs[t][c4] =
                *(const float4*)&x[(size_t)(tok0 + t) * CH + k0 + c4];
        }
        {
            int r = tid >> 2, c = (tid & 3) * 4;
            *(float4*)&Ws[r][c]      = *(const float4*)&WB[(size_t)(k0 + r) * SST + c];
            *(float4*)&Ws[r][16 + c] = *(const float4*)&WC[(size_t)(k0 + r) * SST + c];
        }
        __syncthreads();
        #pragma unroll
        for (int k = 0; k < 64; k++)
            acc = fmaf(xs[ty][k], Ws[k][tx], acc);
        // emit bf16 hi/lo split for this 8x64 tile of x
        {
            float v0 = xs[et][ec], v1 = xs[et][ec + 1];
            __nv_bfloat16 h0 = __float2bfloat16(v0);
            __nv_bfloat16 h1 = __float2bfloat16(v1);
            size_t o = (size_t)(tok0 + et) * CH + k0 + ec;
            *(__nv_bfloat162*)(hi + o) = __nv_bfloat162(h0, h1);
            *(__nv_bfloat162*)(lo + o) = __nv_bfloat162(
                __float2bfloat16(v0 - __bfloat162float(h0)),
                __float2bfloat16(v1 - __bfloat162float(h1)));
        }
    }
    int tok = tok0 + ty;
    if (tx < 16) Bm[(size_t)tok * SST + tx] = acc;
    else         Cm[(size_t)tok * SST + (tx - 16)] = acc;
}

// ---------------- parallel scan, phase 1 -------------------------------------
__global__ __launch_bounds__(64)
void scan1_k(const float* __restrict__ xb, const float* __restrict__ dl,
             const float* __restrict__ Bm, const float* __restrict__ A_log,
             float* __restrict__ hloc, float* __restrict__ dsum)
{
    __shared__ float sB[SGRP * SST];
    const int tid = threadIdx.x;
    const int b = blockIdx.z, ck = blockIdx.y;
    const int c = blockIdx.x * 64 + tid;
    const int t0 = ck * CLEN;

    float A[SST];
    #pragma unroll
    for (int s = 0; s < SST; s++) A[s] = -expf(A_log[(size_t)c * SST + s]);
    float h[SST];
    #pragma unroll
    for (int s = 0; s < SST; s++) h[s] = 0.f;
    float Ds = 0.f;

    for (int g = 0; g < CLEN; g += SGRP) {
        const int tg = t0 + g;
        float rd[SGRP], rx[SGRP];
        size_t base = ((size_t)(b * SEQ + tg)) * CH + c;
        #pragma unroll
        for (int i = 0; i < SGRP; i++) {
            rd[i] = dl[base + (size_t)i * CH];
            rx[i] = xb[base + (size_t)i * CH];
        }
        __syncthreads();
        {
            size_t bb = ((size_t)(b * SEQ + tg)) * SST;
            ((float4*)sB)[tid] = ((const float4*)(Bm + bb))[tid];
        }
        __syncthreads();
        #pragma unroll
        for (int i = 0; i < SGRP; i++) {
            float d = rd[i];
            float dx = d * rx[i];
            Ds += d;
            #pragma unroll
            for (int s = 0; s < SST; s++) {
                float bar = __expf(d * A[s]);
                h[s] = fmaf(bar, h[s], dx * sB[i * SST + s]);
            }
        }
    }
    size_t o = (((size_t)(b * NCH + ck)) * CH + c) * SST;
    #pragma unroll
    for (int s4 = 0; s4 < SST; s4 += 4)
        *(float4*)&hloc[o + s4] = make_float4(h[s4], h[s4+1], h[s4+2], h[s4+3]);
    dsum[((size_t)(b * NCH + ck)) * CH + c] = Ds;
}

// ---------------- parallel scan, phase 2 -------------------------------------
__global__ __launch_bounds__(128)
void scan2_k(const float* __restrict__ hloc, const float* __restrict__ dsum,
             const float* __restrict__ A_log, float* __restrict__ hin)
{
    const int lane = blockIdx.x * 128 + threadIdx.x;
    const int b = lane >> 10, c = lane & (CH - 1);

    float A[SST];
    #pragma unroll
    for (int s = 0; s < SST; s++) A[s] = -expf(A_log[(size_t)c * SST + s]);
    float h[SST];
    #pragma unroll
    for (int s = 0; s < SST; s++) h[s] = 0.f;

    for (int ck = 0; ck < NCH; ck++) {
        size_t o = (((size_t)(b * NCH + ck)) * CH + c) * SST;
        #pragma unroll
        for (int s4 = 0; s4 < SST; s4 += 4)
            *(float4*)&hin[o + s4] = make_float4(h[s4], h[s4+1], h[s4+2], h[s4+3]);
        float Ds = dsum[((size_t)(b * NCH + ck)) * CH + c];
        #pragma unroll
        for (int s4 = 0; s4 < SST; s4 += 4) {
            float4 hl = *(const float4*)&hloc[o + s4];
            h[s4+0] = fmaf(__expf(Ds * A[s4+0]), h[s4+0], hl.x);
            h[s4+1] = fmaf(__expf(Ds * A[s4+1]), h[s4+1], hl.y);
            h[s4+2] = fmaf(__expf(Ds * A[s4+2]), h[s4+2], hl.z);
            h[s4+3] = fmaf(__expf(Ds * A[s4+3]), h[s4+3], hl.w);
        }
    }
}

// ---------------- parallel scan, phase 3 -------------------------------------
__global__ __launch_bounds__(64)
void scan3_k(const float* __restrict__ xb, const float* __restrict__ dl,
             const float* __restrict__ Bm, const float* __restrict__ Cm,
             const float* __restrict__ A_log, const float* __restrict__ hin,
             float* __restrict__ y)
{
    __shared__ float sB[SGRP * SST];
    __shared__ float sC[SGRP * SST];
    const int tid = threadIdx.x;
    const int b = blockIdx.z, ck = blockIdx.y;
    const int c = blockIdx.x * 64 + tid;
    const int t0 = ck * CLEN;

    float A[SST];
    #pragma unroll
    for (int s = 0; s < SST; s++) A[s] = -expf(A_log[(size_t)c * SST + s]);
    float h[SST];
    {
        size_t o = (((size_t)(b * NCH + ck)) * CH + c) * SST;
        #pragma unroll
        for (int s4 = 0; s4 < SST; s4 += 4) {
            float4 v = *(const float4*)&hin[o + s4];
            h[s4] = v.x; h[s4+1] = v.y; h[s4+2] = v.z; h[s4+3] = v.w;
        }
    }

    for (int g = 0; g < CLEN; g += SGRP) {
        const int tg = t0 + g;
        float rd[SGRP], rx[SGRP];
        size_t base = ((size_t)(b * SEQ + tg)) * CH + c;
        #pragma unroll
        for (int i = 0; i < SGRP; i++) {
            rd[i] = dl[base + (size_t)i * CH];
            rx[i] = xb[base + (size_t)i * CH];
        }
        __syncthreads();
        {
            size_t bb = ((size_t)(b * SEQ + tg)) * SST;
            ((float4*)sB)[tid] = ((const float4*)(Bm + bb))[tid];
            ((float4*)sC)[tid] = ((const float4*)(Cm + bb))[tid];
        }
        __syncthreads();
        #pragma unroll
        for (int i = 0; i < SGRP; i++) {
            float d = rd[i];
            float dx = d * rx[i];
            float yv = 0.f;
            #pragma unroll
            for (int s = 0; s < SST; s++) {
                float bar = __expf(d * A[s]);
                float hh = fmaf(bar, h[s], dx * sB[i * SST + s]);
                h[s] = hh;
                yv = fmaf(hh, sC[i * SST + s], yv);
            }
            y[base + (size_t)i * CH] = yv;
        }
    }
}

// ----------- LayerNorm(x_base + y) -> bf16 hi/lo split directly -------------
__global__ __launch_bounds__(256)
void ln_k(const float* __restrict__ xb, const float* __restrict__ y,
          const float* __restrict__ gam, const float* __restrict__ bet,
          __nv_bfloat16* __restrict__ hi, __nv_bfloat16* __restrict__ lo)
{
    const int tok = blockIdx.x, tid = threadIdx.x;
    const float4* a4 = (const float4*)(xb + (size_t)tok * CH);
    const float4* b4 = (const float4*)(y  + (size_t)tok * CH);
    float4 v = a4[tid], w = b4[tid];
    v.x += w.x; v.y += w.y; v.z += w.z; v.w += w.w;
    float sum = v.x + v.y + v.z + v.w;
    float sq  = v.x * v.x + v.y * v.y + v.z * v.z + v.w * v.w;
    #pragma unroll
    for (int off = 16; off; off >>= 1) {
        sum += __shfl_xor_sync(0xffffffffu, sum, off);
        sq  += __shfl_xor_sync(0xffffffffu, sq,  off);
    }
    __shared__ float s1[8], s2[8];
    __shared__ float mu_s, rstd_s;
    if ((tid & 31) == 0) { s1[tid >> 5] = sum; s2[tid >> 5] = sq; }
    __syncthreads();
    if (tid == 0) {
        float t1 = 0.f, t2 = 0.f;
        #pragma unroll
        for (int i = 0; i < 8; i++) { t1 += s1[i]; t2 += s2[i]; }
        float mu = t1 * (1.f / CH);
        float var = t2 * (1.f / CH) - mu * mu;
        mu_s = mu;
        rstd_s = rsqrtf(var + 1e-5f);
    }
    __syncthreads();
    float mu = mu_s, rstd = rstd_s;
    float4 g = ((const float4*)gam)[tid];
    float4 be = ((const float4*)bet)[tid];
    float o0 = (v.x - mu) * rstd * g.x + be.x;
    float o1 = (v.y - mu) * rstd * g.y + be.y;
    float o2 = (v.z - mu) * rstd * g.z + be.z;
    float o3 = (v.w - mu) * rstd * g.w + be.w;
    __nv_bfloat16 h0 = __float2bfloat16(o0);
    __nv_bfloat16 h1 = __float2bfloat16(o1);
    __nv_bfloat16 h2 = __float2bfloat16(o2);
    __nv_bfloat16 h3 = __float2bfloat16(o3);
    size_t base = (size_t)tok * CH + tid * 4;
    __nv_bfloat162* hp = (__nv_bfloat162*)(hi + base);
    __nv_bfloat162* lp = (__nv_bfloat162*)(lo + base);
    hp[0] = __nv_bfloat162(h0, h1); hp[1] = __nv_bfloat162(h2, h3);
    lp[0] = __nv_bfloat162(__float2bfloat16(o0 - __bfloat162float(h0)),
                           __float2bfloat16(o1 - __bfloat162float(h1)));
    lp[1] = __nv_bfloat162(__float2bfloat16(o2 - __bfloat162float(h2)),
                           __float2bfloat16(o3 - __bfloat162float(h3)));
}

// ============================================================================
// Tensor-core causal flash attention (R10 config: q-tile 64, 128 threads).
// Epilogue emits bf16 hi/lo split (B,T,C).
// ============================================================================
#define FRS   144
#define FTILE (64*FRS)
#define FSTG  (4*FTILE)
#define F_SMEM (2*FTILE + 2*FSTG)

__global__ __launch_bounds__(128)
void flash_mma(const __nv_bfloat16* __restrict__ Qh,
               const __nv_bfloat16* __restrict__ Ql,
               const __nv_bfloat16* __restrict__ Kh,
               const __nv_bfloat16* __restrict__ Kl,
               const __nv_bfloat16* __restrict__ Vh,
               const __nv_bfloat16* __restrict__ Vl,
               const float* __restrict__ temp,
               __nv_bfloat16* __restrict__ oHi, __nv_bfloat16* __restrict__ oLo)
{
    extern __shared__ char smem[];
    const int tid = threadIdx.x;
    const int wid = tid >> 5, lane = tid & 31;
    const int qt = (int)gridDim.x - 1 - (int)blockIdx.x;
    const int bh = blockIdx.y;
    const int b = bh >> 4, h = bh & 15;
    const int q0 = qt << 6;
    const uint32_t sb = s2u(smem);
    const uint32_t sQ = sb;
    const uint32_t sS0 = sb + 2 * FTILE;

    const float sc = softplus_f(temp[h]) * 0.125f;

    const __nv_bfloat16* Qhg = Qh + (size_t)bh * SEQ * HDIM + (size_t)q0 * HDIM;
    const __nv_bfloat16* Qlg = Ql + (size_t)bh * SEQ * HDIM + (size_t)q0 * HDIM;
    const __nv_bfloat16* kvg[4] = {
        Kh + (size_t)bh * SEQ * HDIM, Kl + (size_t)bh * SEQ * HDIM,
        Vh + (size_t)bh * SEQ * HDIM, Vl + (size_t)bh * SEQ * HDIM };

    #pragma unroll
    for (int i = 0; i < 8; i++) {
        int slot = tid + i * 128;
        int buf = slot >> 9, idx = slot & 511;
        int row = idx >> 3, ch = idx & 7;
        const __nv_bfloat16* src = (buf ? Qlg : Qhg) + row * HDIM + ch * 8;
        CP_ASYNC16(sQ + buf * FTILE + row * FRS + ch * 16, src);
    }
    {
        #pragma unroll
        for (int i = 0; i < 16; i++) {
            int slot = tid + i * 128;
            int buf = slot >> 9, idx = slot & 511;
            int row = idx >> 3, ch = idx & 7;
            CP_ASYNC16(sS0 + buf * FTILE + row * FRS + ch * 16,
                       kvg[buf] + row * HDIM + ch * 8);
        }
        CP_COMMIT();
    }
    if (qt >= 1) {
        #pragma unroll
        for (int i = 0; i < 16; i++) {
            int slot = tid + i * 128;
            int buf = slot >> 9, idx = slot & 511;
            int row = idx >> 3, ch = idx & 7;
            CP_ASYNC16(sS0 + FSTG + buf * FTILE + row * FRS + ch * 16,
                       kvg[buf] + (64 + row) * HDIM + ch * 8);
        }
        CP_COMMIT();
    }

    const uint32_t aoff = (uint32_t)(wid * 16 + (lane & 15)) * FRS
                        + ((lane >> 4) & 1) * 16;
    const uint32_t kboff = (uint32_t)(((lane >> 4) & 1) * 8 + (lane & 7)) * FRS
                         + ((lane >> 3) & 1) * 16;
    const uint32_t vtoff = (uint32_t)((lane & 7) + ((lane >> 3) & 1) * 8) * FRS
                         + ((lane >> 4) & 1) * 16;

    uint32_t qh[4][4], ql[4][4];
    float O[8][4];
    #pragma unroll
    for (int jj = 0; jj < 8; jj++)
        #pragma unroll
        for (int q = 0; q < 4; q++) O[jj][q] = 0.f;
    float m0v = -1e30f, m1v = -1e30f, l0v = 0.f, l1v = 0.f;

    const int r_in_w = lane >> 2;
    const int row0g = q0 + wid * 16 + r_in_w;
    const int cql = (lane & 3) * 2;

    for (int kb = 0; kb <= qt; kb++) {
        if (kb < qt) CP_WAIT1(); else CP_WAIT0();
        __syncthreads();

        if (kb == 0) {
            #pragma unroll
            for (int ks = 0; ks < 4; ks++) {
                LDSM4(qh[ks][0], qh[ks][1], qh[ks][2], qh[ks][3],
                      sQ + aoff + ks * 32);
                LDSM4(ql[ks][0], ql[ks][1], ql[ks][2], ql[ks][3],
                      sQ + FTILE + aoff + ks * 32);
            }
        }

        const uint32_t st = sS0 + (kb & 1) * FSTG;
        float S[8][4];
        #pragma unroll
        for (int jj = 0; jj < 8; jj++)
            #pragma unroll
            for (int q = 0; q < 4; q++) S[jj][q] = 0.f;

        #pragma unroll
        for (int ks = 0; ks < 4; ks++) {
            #pragma unroll
            for (int g = 0; g < 4; g++) {
                uint32_t bh0, bh1, bh2, bh3, bl0, bl1, bl2, bl3;
                uint32_t kaddr = st + kboff + g * 16 * FRS + ks * 32;
                LDSM4(bh0, bh1, bh2, bh3, kaddr);
                LDSM4(bl0, bl1, bl2, bl3, kaddr + FTILE);
                MMA16816(S[2*g],   qh[ks][0], qh[ks][1], qh[ks][2], qh[ks][3], bh0, bh1);
                MMA16816(S[2*g+1], qh[ks][0], qh[ks][1], qh[ks][2], qh[ks][3], bh2, bh3);
                MMA16816(S[2*g],   qh[ks][0], qh[ks][1], qh[ks][2], qh[ks][3], bl0, bl1);
                MMA16816(S[2*g+1], qh[ks][0], qh[ks][1], qh[ks][2], qh[ks][3], bl2, bl3);
                MMA16816(S[2*g],   ql[ks][0], ql[ks][1], ql[ks][2], ql[ks][3], bh0, bh1);
                MMA16816(S[2*g+1], ql[ks][0], ql[ks][1], ql[ks][2], ql[ks][3], bh2, bh3);
            }
        }

        #pragma unroll
        for (int jj = 0; jj < 8; jj++)
            #pragma unroll
            for (int q = 0; q < 4; q++) S[jj][q] *= sc;
        if (kb == qt) {
            #pragma unroll
            for (int jj = 0; jj < 8; jj++) {
                #pragma unroll
                for (int q = 0; q < 4; q++) {
                    int col = (kb << 6) + jj * 8 + cql + (q & 1);
                    int row = row0g + (q >> 1) * 8;
                    if (col > row) S[jj][q] = -1e30f;
                }
            }
        }

        float mx0 = -1e30f, mx1 = -1e30f;
        #pragma unroll
        for (int jj = 0; jj < 8; jj++) {
            mx0 = fmaxf(mx0, fmaxf(S[jj][0], S[jj][1]));
            mx1 = fmaxf(mx1, fmaxf(S[jj][2], S[jj][3]));
        }
        mx0 = fmaxf(mx0, __shfl_xor_sync(0xffffffffu, mx0, 1));
        mx0 = fmaxf(mx0, __shfl_xor_sync(0xffffffffu, mx0, 2));
        mx1 = fmaxf(mx1, __shfl_xor_sync(0xffffffffu, mx1, 1));
        mx1 = fmaxf(mx1, __shfl_xor_sync(0xffffffffu, mx1, 2));
        float mn0 = fmaxf(m0v, mx0), mn1 = fmaxf(m1v, mx1);
        float fac0 = __expf(m0v - mn0), fac1 = __expf(m1v - mn1);
        m0v = mn0; m1v = mn1;
        float rs0 = 0.f, rs1 = 0.f;
        #pragma unroll
        for (int jj = 0; jj < 8; jj++) {
            S[jj][0] = __expf(S[jj][0] - mn0); rs0 += S[jj][0];
            S[jj][1] = __expf(S[jj][1] - mn0); rs0 += S[jj][1];
            S[jj][2] = __expf(S[jj][2] - mn1); rs1 += S[jj][2];
            S[jj][3] = __expf(S[jj][3] - mn1); rs1 += S[jj][3];
        }
        rs0 += __shfl_xor_sync(0xffffffffu, rs0, 1);
        rs0 += __shfl_xor_sync(0xffffffffu, rs0, 2);
        rs1 += __shfl_xor_sync(0xffffffffu, rs1, 1);
        rs1 += __shfl_xor_sync(0xffffffffu, rs1, 2);
        l0v = l0v * fac0 + rs0;
        l1v = l1v * fac1 + rs1;
        #pragma unroll
        for (int jj = 0; jj < 8; jj++) {
            O[jj][0] *= fac0; O[jj][1] *= fac0;
            O[jj][2] *= fac1; O[jj][3] *= fac1;
        }

        #pragma unroll
        for (int ks = 0; ks < 4; ks++) {
            uint32_t ph[4], pl[4];
            #pragma unroll
            for (int half = 0; half < 2; half++) {
                int jj = 2 * ks + half;
                float f0 = S[jj][0], f1 = S[jj][1], f2 = S[jj][2], f3 = S[jj][3];
                __nv_bfloat162 h01 = __floats2bfloat162_rn(f0, f1);
                __nv_bfloat162 h23 = __floats2bfloat162_rn(f2, f3);
                __nv_bfloat162 l01 = __floats2bfloat162_rn(
                    f0 - __bfloat162float(h01.x), f1 - __bfloat162float(h01.y));
                __nv_bfloat162 l23 = __floats2bfloat162_rn(
                    f2 - __bfloat162float(h23.x), f3 - __bfloat162float(h23.y));
                if (half == 0) {
                    ph[0] = *(uint32_t*)&h01; ph[1] = *(uint32_t*)&h23;
                    pl[0] = *(uint32_t*)&l01; pl[1] = *(uint32_t*)&l23;
                } else {
                    ph[2] = *(uint32_t*)&h01; ph[3] = *(uint32_t*)&h23;
                    pl[2] = *(uint32_t*)&l01; pl[3] = *(uint32_t*)&l23;
                }
            }
            #pragma unroll
            for (int g = 0; g < 4; g++) {
                uint32_t vh0, vh1, vh2, vh3, vl0, vl1, vl2, vl3;
                uint32_t vaddr = st + 2 * FTILE + vtoff + ks * 16 * FRS + g * 32;
                LDSM4T(vh0, vh1, vh2, vh3, vaddr);
                LDSM4T(vl0, vl1, vl2, vl3, vaddr + FTILE);
                MMA16816(O[2*g],   ph[0], ph[1], ph[2], ph[3], vh0, vh1);
                MMA16816(O[2*g+1], ph[0], ph[1], ph[2], ph[3], vh2, vh3);
                MMA16816(O[2*g],   ph[0], ph[1], ph[2], ph[3], vl0, vl1);
                MMA16816(O[2*g+1], ph[0], ph[1], ph[2], ph[3], vl2, vl3);
                MMA16816(O[2*g],   pl[0], pl[1], pl[2], pl[3], vh0, vh1);
                MMA16816(O[2*g+1], pl[0], pl[1], pl[2], pl[3], vh2, vh3);
            }
        }
        __syncthreads();

        if (kb + 2 <= qt) {
            const uint32_t sd = sS0 + (kb & 1) * FSTG;
            const int kr = (kb + 2) << 6;
            #pragma unroll
            for (int i = 0; i < 16; i++) {
                int slot = tid + i * 128;
                int buf = slot >> 9, idx = slot & 511;
                int row = idx >> 3, ch = idx & 7;
                CP_ASYNC16(sd + buf * FTILE + row * FRS + ch * 16,
                           kvg[buf] + (size_t)(kr + row) * HDIM + ch * 8);
            }
            CP_COMMIT();
        }
    }

    float inv0 = 1.f / l0v, inv1 = 1.f / l1v;
    const int row_a = row0g, row_b = row0g + 8;
    #pragma unroll
    for (int jj = 0; jj < 8; jj++) {
        int col = h * HDIM + jj * 8 + cql;
        float a0 = O[jj][0] * inv0, a1 = O[jj][1] * inv0;
        float b0 = O[jj][2] * inv1, b1 = O[jj][3] * inv1;
        __nv_bfloat162 ha = __floats2bfloat162_rn(a0, a1);
        __nv_bfloat162 hb = __floats2bfloat162_rn(b0, b1);
        size_t pa = ((size_t)(b * SEQ + row_a)) * CH + col;
        size_t pb = ((size_t)(b * SEQ + row_b)) * CH + col;
        *(__nv_bfloat162*)(oHi + pa) = ha;
        *(__nv_bfloat162*)(oHi + pb) = hb;
        *(__nv_bfloat162*)(oLo + pa) = __floats2bfloat162_rn(
            a0 - __bfloat162float(ha.x), a1 - __bfloat162float(ha.y));
        *(__nv_bfloat162*)(oLo + pb) = __floats2bfloat162_rn(
            b0 - __bfloat162float(hb.x), b1 - __bfloat162float(hb.y));
    }
}

// ---------------- launcher ---------------------------------------------------
extern "C" void kernel_launch(void* const* d_in, const int* in_sizes, int n_in,
                              void* d_out, int out_size)
{
    const float* x     = (const float*)d_in[0];
    const float* A_log = (const float*)d_in[1];
    const float* Wd    = (const float*)d_in[2];
    const float* bd    = (const float*)d_in[3];
    const float* WB    = (const float*)d_in[4];
    const float* WC    = (const float*)d_in[5];
    const float* Wq    = (const float*)d_in[6];
    const float* bq    = (const float*)d_in[7];
    const float* Wk    = (const float*)d_in[8];
    const float* bk    = (const float*)d_in[9];
    const float* Wv    = (const float*)d_in[10];
    const float* bv    = (const float*)d_in[11];
    const float* Wx    = (const float*)d_in[12];
    const float* bx    = (const float*)d_in[13];
    const float* Wo    = (const float*)d_in[14];
    const float* bo    = (const float*)d_in[15];
    const float* ln_g  = (const float*)d_in[16];
    const float* ln_b  = (const float*)d_in[17];
    const float* temp  = (const float*)d_in[18];
    float* out = (float*)d_out;

    float* xb = nullptr; cudaGetSymbolAddress((void**)&xb, g_xb);
    float* dl = nullptr; cudaGetSymbolAddress((void**)&dl, g_dl);
    float* Bm = nullptr; cudaGetSymbolAddress((void**)&Bm, g_Bm);
    float* Cm = nullptr; cudaGetSymbolAddress((void**)&Cm, g_Cm);
    float* yb = nullptr; cudaGetSymbolAddress((void**)&yb, g_y);
    float* hloc = nullptr; cudaGetSymbolAddress((void**)&hloc, g_hloc);
    float* hin  = nullptr; cudaGetSymbolAddress((void**)&hin,  g_hin);
    float* dsum = nullptr; cudaGetSymbolAddress((void**)&dsum, g_dsum);
    __nv_bfloat16* ahi = nullptr; cudaGetSymbolAddress((void**)&ahi, g_ahi);
    __nv_bfloat16* alo = nullptr; cudaGetSymbolAddress((void**)&alo, g_alo);
    __nv_bfloat16* wt  = nullptr; cudaGetSymbolAddress((void**)&wt,  g_wt);
    __nv_bfloat16 *qh, *ql, *kh, *kl, *vh, *vl;
    cudaGetSymbolAddress((void**)&qh, g_Qh);
    cudaGetSymbolAddress((void**)&ql, g_Ql);
    cudaGetSymbolAddress((void**)&kh, g_Kh);
    cudaGetSymbolAddress((void**)&kl, g_Kl);
    cudaGetSymbolAddress((void**)&vh, g_Vh);
    cudaGetSymbolAddress((void**)&vl, g_Vl);

    cudaFuncSetAttribute(mm_multi, cudaFuncAttributeMaxDynamicSharedMemorySize,
                         MM_SMEM);
    cudaFuncSetAttribute(flash_mma, cudaFuncAttributeMaxDynamicSharedMemorySize,
                         F_SMEM);

    const size_t WSZ = (size_t)CH * CH;

    // weight order in g_wt: {Wx, Wd, Wq, Wk, Wv, Wo} x {hi, lo}
    cvt_wt6<<<dim3(32, 32, 6), dim3(32, 8)>>>(Wx, Wd, Wq, Wk, Wv, Wo, wt);
    // fused B/C projection + x -> bf16 split
    prep_k<<<NTOK / 8, 256>>>(x, WB, WC, Bm, Cm, ahi, alo);

    MMJob jx  = {wt + 0*WSZ,  wt + 1*WSZ,  bx, xb, nullptr, nullptr, 0};
    MMJob jd  = {wt + 2*WSZ,  wt + 3*WSZ,  bd, dl, nullptr, nullptr, 1};
    MMJob jq  = {wt + 4*WSZ,  wt + 5*WSZ,  bq, nullptr, qh, ql, 4};
    MMJob jk  = {wt + 6*WSZ,  wt + 7*WSZ,  bk, nullptr, kh, kl, 4};
    MMJob jv  = {wt + 8*WSZ,  wt + 9*WSZ,  bv, nullptr, vh, vl, 4};
    MMJob jo  = {wt + 10*WSZ, wt + 11*WSZ, bo, out, nullptr, nullptr, 0};
    MMJob jz  = {};

    mm_multi<<<dim3(8, 32, 2), 256, MM_SMEM>>>(ahi, alo, jx, jd, jz);

    dim3 scan_grid(CH / 64, NCH, BATCH);
    scan1_k<<<scan_grid, 64>>>(xb, dl, Bm, A_log, hloc, dsum);
    scan2_k<<<BATCH * CH / 128, 128>>>(hloc, dsum, A_log, hin);
    scan3_k<<<scan_grid, 64>>>(xb, dl, Bm, Cm, A_log, hin, yb);

    ln_k<<<NTOK, 256>>>(xb, yb, ln_g, ln_b, ahi, alo);

    mm_multi<<<dim3(8, 32, 3), 256, MM_SMEM>>>(ahi, alo, jq, jk, jv);

    flash_mma<<<dim3(SEQ / 64, BATCH * NH), 128, F_SMEM>>>(qh, ql, kh, kl,
                                                           vh, vl, temp,
                                                           ahi, alo);

    mm_multi<<<dim3(8, 32, 1), 256, MM_SMEM>>>(ahi, alo, jo, jz, jz);
}